// round 3
// baseline (speedup 1.0000x reference)
#include <cuda_runtime.h>

#define NB 8
#define NC 256
#define NH 128
#define NW 128
#define NHW 16384
#define KK 1280
#define NP 25

// Output layout (float32, concatenated in reference-return order)
#define N_PATCH   65536000ULL                  // 8*1280*25*256
#define OFF_COORD 65536000ULL
#define OFF_OFFS  65556480ULL                  // + 8*1280*2
#define OFF_CAL   65556530ULL                  // + 50

static __device__ int2 g_coords[NB * KK];      // scratch: clamped (cy,cx) per (b,k)

// ---------------------------------------------------------------------------
// Kernel A: softmax + calibrated map + top-K selection (one block per batch)
// ---------------------------------------------------------------------------
__global__ __launch_bounds__(1024) void topk_kernel(
    const float* __restrict__ sal, const float* __restrict__ mask,
    float* __restrict__ out)
{
    const int b   = blockIdx.x;
    const int tid = threadIdx.x;

    __shared__ float red[32];
    __shared__ int   hist[256];
    __shared__ int   sh_b1, sh_cntgt, sh_T16, sh_cnt;
    __shared__ unsigned long long items[4096];

    const float* sb = sal + (size_t)b * NHW;

    // x = (saliency + mask) / TEMP, TEMP = 0.5 (exact *2)
    float x[16];
    float mx = -3.4e38f;
#pragma unroll
    for (int j = 0; j < 16; j++) {
        int i = tid + j * 1024;
        float v = (sb[i] + mask[i]) * 2.0f;
        x[j] = v;
        mx = fmaxf(mx, v);
    }
#pragma unroll
    for (int o = 16; o > 0; o >>= 1) mx = fmaxf(mx, __shfl_xor_sync(0xffffffffu, mx, o));
    if ((tid & 31) == 0) red[tid >> 5] = mx;
    __syncthreads();
    if (tid < 32) {
        float t = red[tid];
#pragma unroll
        for (int o = 16; o > 0; o >>= 1) t = fmaxf(t, __shfl_xor_sync(0xffffffffu, t, o));
        if (tid == 0) red[0] = t;
    }
    __syncthreads();
    const float gmax = red[0];
    __syncthreads();

    float sacc = 0.f;
#pragma unroll
    for (int j = 0; j < 16; j++) sacc += expf(x[j] - gmax);
#pragma unroll
    for (int o = 16; o > 0; o >>= 1) sacc += __shfl_xor_sync(0xffffffffu, sacc, o);
    if ((tid & 31) == 0) red[tid >> 5] = sacc;
    __syncthreads();
    if (tid < 32) {
        float t = red[tid];
#pragma unroll
        for (int o = 16; o > 0; o >>= 1) t += __shfl_xor_sync(0xffffffffu, t, o);
        if (tid == 0) red[0] = t;
    }
    __syncthreads();
    const float gsum = red[0];

    // soft values: overwrite x; write calibrated map to output
#pragma unroll
    for (int j = 0; j < 16; j++) {
        int i = tid + j * 1024;
        float s = expf(x[j] - gmax) / gsum;
        x[j] = s;
        out[OFF_CAL + (unsigned long long)b * NHW + i] = s;
    }

    // ---- radix select: level 1, top 8 bits of float bits (soft >= 0) ----
    if (tid < 256) hist[tid] = 0;
    __syncthreads();
#pragma unroll
    for (int j = 0; j < 16; j++) atomicAdd(&hist[__float_as_uint(x[j]) >> 24], 1);
    __syncthreads();
    if (tid == 0) {
        int cum = 0, bsel = 0;
        for (int bb = 255; bb >= 0; bb--) {
            int h = hist[bb];
            if (cum + h >= KK) { bsel = bb; break; }
            cum += h;
        }
        sh_b1 = bsel; sh_cntgt = cum;
    }
    __syncthreads();
    const int b1 = sh_b1, cntgt = sh_cntgt;

    // ---- level 2: next 8 bits within threshold bin ----
    if (tid < 256) hist[tid] = 0;
    __syncthreads();
#pragma unroll
    for (int j = 0; j < 16; j++) {
        unsigned key = __float_as_uint(x[j]);
        if ((int)(key >> 24) == b1) atomicAdd(&hist[(key >> 16) & 255], 1);
    }
    __syncthreads();
    if (tid == 0) {
        int K2 = KK - cntgt;
        int cum = 0, bsel = 0;
        for (int bb = 255; bb >= 0; bb--) {
            int h = hist[bb];
            if (cum + h >= K2) { bsel = bb; break; }
            cum += h;
        }
        sh_T16 = (b1 << 8) | bsel;
        sh_cnt = 0;
    }
    __syncthreads();
    const unsigned T16 = (unsigned)sh_T16;

    // ---- collect survivors (16-bit prefix >= T16): ~K + O(10) items ----
#pragma unroll
    for (int j = 0; j < 16; j++) {
        unsigned key = __float_as_uint(x[j]);
        if ((key >> 16) >= T16) {
            int p = atomicAdd(&sh_cnt, 1);
            if (p < 4096) {
                unsigned idx = (unsigned)(tid + j * 1024);
                // descending by soft, then ascending by index (jax tie-break)
                items[p] = ((unsigned long long)key << 32) | (unsigned)(~idx);
            }
        }
    }
    __syncthreads();
    int cnt = sh_cnt; if (cnt > 4096) cnt = 4096;
    for (int i = tid; i < 4096; i += 1024)
        if (i >= cnt) items[i] = 0ULL;
    __syncthreads();

    // ---- bitonic sort, descending ----
    for (int kk = 2; kk <= 4096; kk <<= 1) {
        for (int j = kk >> 1; j > 0; j >>= 1) {
            for (int i = tid; i < 4096; i += 1024) {
                int l = i ^ j;
                if (l > i) {
                    unsigned long long A = items[i], Bv = items[l];
                    bool desc = ((i & kk) == 0);
                    if (desc ? (A < Bv) : (A > Bv)) { items[i] = Bv; items[l] = A; }
                }
            }
            __syncthreads();
        }
    }

    // ---- emit coords ----
    for (int k = tid; k < KK; k += 1024) {
        unsigned long long it = items[k];
        unsigned idx = ~((unsigned)it);
        int cy = (int)(idx >> 7);
        int cx = (int)(idx & 127);
        cy = min(max(cy, 2), 125);
        cx = min(max(cx, 2), 125);
        unsigned long long o = OFF_COORD + ((unsigned long long)b * KK + k) * 2ULL;
        out[o]     = (float)cy;
        out[o + 1] = (float)cx;
        g_coords[b * KK + k] = make_int2(cy, cx);
    }

    // offsets output (constant), written once
    if (b == 0 && tid < 50) {
        int p = tid >> 1, j = tid & 1;
        int v = (j == 0 ? p / 5 : p % 5) - 2;
        out[OFF_OFFS + tid] = (float)v;
    }
}

// ---------------------------------------------------------------------------
// Kernel B: window gather + weighting. One block per (b,k) window.
// Thread = channel; each thread loads 5 rows as 2x float4 and writes 25
// coalesced STG.32 (consecutive channels across lanes).
// ---------------------------------------------------------------------------
__global__ __launch_bounds__(256) void gather_kernel(
    const float* __restrict__ feat, const float* __restrict__ gamma,
    float* __restrict__ out)
{
    const int blk = blockIdx.x;
    const int b = blk / KK;

    __shared__ float wts[NP];
    __shared__ int2  sc;
    if (threadIdx.x == 0) sc = g_coords[blk];
    __syncthreads();
    const int cy = sc.x, cx = sc.y;

    if (threadIdx.x < 32) {
        int lane = threadIdx.x;
        int dy = lane / 5 - 2, dx = lane % 5 - 2;
        const float g = __ldg(gamma);
        float scv = 0.f;
        if (lane < NP) {
            int y = cy + dy, xx = cx + dx;
            scv = out[OFF_CAL + (unsigned long long)b * NHW + y * NW + xx];
        }
        float sum = scv;
#pragma unroll
        for (int o = 16; o > 0; o >>= 1) sum += __shfl_xor_sync(0xffffffffu, sum, o);
        if (lane < NP) {
            float mean = sum / 25.0f;
            float dist = sqrtf((float)(dy * dy + dx * dx));
            float dw = expf(-dist / 2.5f);          // LAMBDA*WIN = 2.5
            float z = g * (scv - mean);
            float sg = 1.0f / (1.0f + expf(-z));
            wts[lane] = sg * dw;
        }
    }
    __syncthreads();

    const int c = threadIdx.x;
    const float* fb = feat + ((unsigned long long)b * NC + c) * NHW;
    float* ob = out + ((unsigned long long)blk * NP) * NC + c;

    const int xb = cx - 2;
    const int al = xb & ~3;     // float4-aligned start covering xb..xb+4
    const int r  = xb & 3;

#pragma unroll
    for (int wy = 0; wy < 5; wy++) {
        int y = cy - 2 + wy;
        const float4* row = reinterpret_cast<const float4*>(fb + y * NW + al);
        float4 lo = __ldg(row);
        float4 hi = __ldg(row + 1);
        float v0 = (r == 0) ? lo.x : (r == 1) ? lo.y : (r == 2) ? lo.z : lo.w;
        float v1 = (r == 0) ? lo.y : (r == 1) ? lo.z : (r == 2) ? lo.w : hi.x;
        float v2 = (r == 0) ? lo.z : (r == 1) ? lo.w : (r == 2) ? hi.x : hi.y;
        float v3 = (r == 0) ? lo.w : (r == 1) ? hi.x : (r == 2) ? hi.y : hi.z;
        float v4 = (r == 0) ? hi.x : (r == 1) ? hi.y : (r == 2) ? hi.z : hi.w;
        int p0 = wy * 5;
        ob[(unsigned long long)(p0 + 0) * NC] = v0 * wts[p0 + 0];
        ob[(unsigned long long)(p0 + 1) * NC] = v1 * wts[p0 + 1];
        ob[(unsigned long long)(p0 + 2) * NC] = v2 * wts[p0 + 2];
        ob[(unsigned long long)(p0 + 3) * NC] = v3 * wts[p0 + 3];
        ob[(unsigned long long)(p0 + 4) * NC] = v4 * wts[p0 + 4];
    }
}

extern "C" void kernel_launch(void* const* d_in, const int* in_sizes, int n_in,
                              void* d_out, int out_size)
{
    (void)in_sizes; (void)n_in; (void)out_size;
    const float* feat  = (const float*)d_in[0];   // [8,256,128,128]
    const float* sal   = (const float*)d_in[1];   // [8,128,128]
    const float* mask  = (const float*)d_in[2];   // [1,128,128]
    const float* gamma = (const float*)d_in[3];   // [1]
    float* out = (float*)d_out;

    topk_kernel<<<NB, 1024>>>(sal, mask, out);
    gather_kernel<<<NB * KK, 256>>>(feat, gamma, out);
}

// round 5
// speedup vs baseline: 1.0109x; 1.0109x over previous
#include <cuda_runtime.h>

#define NB 8
#define NC 256
#define NH 128
#define NW 128
#define NHW 16384
#define KK 1280
#define NP 25

// Output layout (float32, concatenated in reference-return order)
#define N_PATCH   65536000ULL                  // 8*1280*25*256
#define OFF_COORD 65536000ULL
#define OFF_OFFS  65556480ULL                  // + 8*1280*2
#define OFF_CAL   65556530ULL                  // + 50

static __device__ int2 g_coords[NB * KK];      // scratch: clamped (cy,cx) per (b,k)

// ---------------------------------------------------------------------------
// Kernel A: softmax + calibrated map + top-K selection (one block per batch)
// ---------------------------------------------------------------------------
__global__ __launch_bounds__(1024) void topk_kernel(
    const float* __restrict__ sal, const float* __restrict__ mask,
    float* __restrict__ out)
{
    const int b   = blockIdx.x;
    const int tid = threadIdx.x;

    __shared__ float red[32];
    __shared__ int   hist[256];
    __shared__ int   sh_b1, sh_cntgt, sh_T16, sh_cnt;
    __shared__ unsigned long long items[4096];

    const float* sb = sal + (size_t)b * NHW;

    // x = (saliency + mask) / TEMP, TEMP = 0.5 (exact *2)
    float x[16];
    float mx = -3.4e38f;
#pragma unroll
    for (int j = 0; j < 16; j++) {
        int i = tid + j * 1024;
        float v = (sb[i] + mask[i]) * 2.0f;
        x[j] = v;
        mx = fmaxf(mx, v);
    }
#pragma unroll
    for (int o = 16; o > 0; o >>= 1) mx = fmaxf(mx, __shfl_xor_sync(0xffffffffu, mx, o));
    if ((tid & 31) == 0) red[tid >> 5] = mx;
    __syncthreads();
    if (tid < 32) {
        float t = red[tid];
#pragma unroll
        for (int o = 16; o > 0; o >>= 1) t = fmaxf(t, __shfl_xor_sync(0xffffffffu, t, o));
        if (tid == 0) red[0] = t;
    }
    __syncthreads();
    const float gmax = red[0];
    __syncthreads();

    float sacc = 0.f;
#pragma unroll
    for (int j = 0; j < 16; j++) sacc += expf(x[j] - gmax);
#pragma unroll
    for (int o = 16; o > 0; o >>= 1) sacc += __shfl_xor_sync(0xffffffffu, sacc, o);
    if ((tid & 31) == 0) red[tid >> 5] = sacc;
    __syncthreads();
    if (tid < 32) {
        float t = red[tid];
#pragma unroll
        for (int o = 16; o > 0; o >>= 1) t += __shfl_xor_sync(0xffffffffu, t, o);
        if (tid == 0) red[0] = t;
    }
    __syncthreads();
    const float gsum = red[0];

    // soft values: overwrite x; write calibrated map to output
#pragma unroll
    for (int j = 0; j < 16; j++) {
        int i = tid + j * 1024;
        float s = expf(x[j] - gmax) / gsum;
        x[j] = s;
        out[OFF_CAL + (unsigned long long)b * NHW + i] = s;
    }

    // ---- radix select: level 1, top 8 bits of float bits (soft >= 0) ----
    if (tid < 256) hist[tid] = 0;
    __syncthreads();
#pragma unroll
    for (int j = 0; j < 16; j++) atomicAdd(&hist[__float_as_uint(x[j]) >> 24], 1);
    __syncthreads();
    if (tid == 0) {
        int cum = 0, bsel = 0;
        for (int bb = 255; bb >= 0; bb--) {
            int h = hist[bb];
            if (cum + h >= KK) { bsel = bb; break; }
            cum += h;
        }
        sh_b1 = bsel; sh_cntgt = cum;
    }
    __syncthreads();
    const int b1 = sh_b1, cntgt = sh_cntgt;

    // ---- level 2: next 8 bits within threshold bin ----
    if (tid < 256) hist[tid] = 0;
    __syncthreads();
#pragma unroll
    for (int j = 0; j < 16; j++) {
        unsigned key = __float_as_uint(x[j]);
        if ((int)(key >> 24) == b1) atomicAdd(&hist[(key >> 16) & 255], 1);
    }
    __syncthreads();
    if (tid == 0) {
        int K2 = KK - cntgt;
        int cum = 0, bsel = 0;
        for (int bb = 255; bb >= 0; bb--) {
            int h = hist[bb];
            if (cum + h >= K2) { bsel = bb; break; }
            cum += h;
        }
        sh_T16 = (b1 << 8) | bsel;
        sh_cnt = 0;
    }
    __syncthreads();
    const unsigned T16 = (unsigned)sh_T16;

    // ---- collect survivors (16-bit prefix >= T16): ~K + O(10) items ----
#pragma unroll
    for (int j = 0; j < 16; j++) {
        unsigned key = __float_as_uint(x[j]);
        if ((key >> 16) >= T16) {
            int p = atomicAdd(&sh_cnt, 1);
            if (p < 4096) {
                unsigned idx = (unsigned)(tid + j * 1024);
                // descending by soft, then ascending by index (jax tie-break)
                items[p] = ((unsigned long long)key << 32) | (unsigned)(~idx);
            }
        }
    }
    __syncthreads();
    int cnt = sh_cnt; if (cnt > 4096) cnt = 4096;
    const int n = (cnt <= 2048) ? 2048 : 4096;   // sort only what we must
    for (int i = cnt + tid; i < n; i += 1024) items[i] = 0ULL;
    __syncthreads();

    // ---- bitonic sort over n (2048 typical), descending ----
    for (int kk = 2; kk <= n; kk <<= 1) {
        for (int j = kk >> 1; j > 0; j >>= 1) {
            for (int i = tid; i < n; i += 1024) {
                int l = i ^ j;
                if (l > i) {
                    unsigned long long A = items[i], Bv = items[l];
                    bool desc = ((i & kk) == 0);
                    if (desc ? (A < Bv) : (A > Bv)) { items[i] = Bv; items[l] = A; }
                }
            }
            __syncthreads();
        }
    }

    // ---- emit coords ----
    for (int k = tid; k < KK; k += 1024) {
        unsigned long long it = items[k];
        unsigned idx = ~((unsigned)it);
        int cy = (int)(idx >> 7);
        int cx = (int)(idx & 127);
        cy = min(max(cy, 2), 125);
        cx = min(max(cx, 2), 125);
        unsigned long long o = OFF_COORD + ((unsigned long long)b * KK + k) * 2ULL;
        out[o]     = (float)cy;
        out[o + 1] = (float)cx;
        g_coords[b * KK + k] = make_int2(cy, cx);
    }

    // offsets output (constant), written once
    if (b == 0 && tid < 50) {
        int p = tid >> 1, j = tid & 1;
        int v = (j == 0 ? p / 5 : p % 5) - 2;
        out[OFF_OFFS + tid] = (float)v;
    }
}

// ---------------------------------------------------------------------------
// Kernel B v2: window gather + weighting. One block per (b,k) window.
// 512 threads: lane pair (2c, 2c+1) loads the lo/hi 16B chunks of the same
// (channel,row) 128B line IN ONE instruction -> 1 L1 wavefront per line
// (vs 2 before). Partner chunk exchanged via shfl_xor (no L1 cost). Stores
// are predicated half-warps: 16 consecutive channels = 64B = 1 wavefront.
// ---------------------------------------------------------------------------
__device__ __forceinline__ float win_extract(float4 lo, float4 hi, int r, int i)
{
    // value at float index r+i within [lo.x..hi.w], i compile-time, r in 0..3
    int t = r + i;
    return t == 0 ? lo.x : t == 1 ? lo.y : t == 2 ? lo.z : t == 3 ? lo.w :
           t == 4 ? hi.x : t == 5 ? hi.y : t == 6 ? hi.z : hi.w;
}

__global__ __launch_bounds__(512) void gather_kernel(
    const float* __restrict__ feat, const float* __restrict__ gamma,
    float* __restrict__ out)
{
    const int blk = blockIdx.x;
    const int b = blk / KK;

    __shared__ float wts[NP];
    __shared__ int2  sc;
    if (threadIdx.x == 0) sc = g_coords[blk];
    __syncthreads();
    const int cy = sc.x, cx = sc.y;

    const int c = threadIdx.x >> 1;     // channel
    const int h = threadIdx.x & 1;      // lo/hi chunk
    const float* fb = feat + ((unsigned long long)b * NC + c) * NHW;

    const int xb = cx - 2;
    const int al = xb & ~3;             // float4-aligned start covering xb..xb+4
    const int r  = xb & 3;

    // Issue all 5 row loads early (MLP=5); each thread loads its 16B chunk.
    float4 own[5];
#pragma unroll
    for (int wy = 0; wy < 5; wy++) {
        int y = cy - 2 + wy;
        own[wy] = __ldg(reinterpret_cast<const float4*>(fb + y * NW + al) + h);
    }

    // Meanwhile warp 0 computes the 25 per-window weights.
    if (threadIdx.x < 32) {
        int lane = threadIdx.x;
        int dy = lane / 5 - 2, dx = lane % 5 - 2;
        const float g = __ldg(gamma);
        float scv = 0.f;
        if (lane < NP) {
            int y = cy + dy, xx = cx + dx;
            scv = out[OFF_CAL + (unsigned long long)b * NHW + y * NW + xx];
        }
        float sum = scv;
#pragma unroll
        for (int o = 16; o > 0; o >>= 1) sum += __shfl_xor_sync(0xffffffffu, sum, o);
        if (lane < NP) {
            float mean = sum / 25.0f;
            float dist = sqrtf((float)(dy * dy + dx * dx));
            float dw = expf(-dist / 2.5f);          // LAMBDA*WIN = 2.5
            float z = g * (scv - mean);
            float sg = 1.0f / (1.0f + expf(-z));
            wts[lane] = sg * dw;
        }
    }
    __syncthreads();

    float* ob = out + ((unsigned long long)blk * NP) * NC + c;

    // Per row: exchange partner chunk, extract 5 values, each half-lane
    // stores its share (h=0: even i, h=1: odd i) -> every store instruction
    // has 16 active lanes with 16 consecutive channels (64B, 1 wavefront).
#pragma unroll
    for (int wy = 0; wy < 5; wy++) {
        float4 mine = own[wy];
        float4 oth;
        oth.x = __shfl_xor_sync(0xffffffffu, mine.x, 1);
        oth.y = __shfl_xor_sync(0xffffffffu, mine.y, 1);
        oth.z = __shfl_xor_sync(0xffffffffu, mine.z, 1);
        oth.w = __shfl_xor_sync(0xffffffffu, mine.w, 1);
        float4 lo = h ? oth : mine;
        float4 hi = h ? mine : oth;
#pragma unroll
        for (int i = 0; i < 5; i++) {
            if ((i & 1) == h) {
                int p = wy * 5 + i;
                float v = win_extract(lo, hi, r, i);
                ob[(unsigned long long)p * NC] = v * wts[p];
            }
        }
    }
}

extern "C" void kernel_launch(void* const* d_in, const int* in_sizes, int n_in,
                              void* d_out, int out_size)
{
    (void)in_sizes; (void)n_in; (void)out_size;
    const float* feat  = (const float*)d_in[0];   // [8,256,128,128]
    const float* sal   = (const float*)d_in[1];   // [8,128,128]
    const float* mask  = (const float*)d_in[2];   // [1,128,128]
    const float* gamma = (const float*)d_in[3];   // [1]
    float* out = (float*)d_out;

    topk_kernel<<<NB, 1024>>>(sal, mask, out);
    gather_kernel<<<NB * KK, 512>>>(feat, gamma, out);
}

// round 7
// speedup vs baseline: 1.0692x; 1.0577x over previous
#include <cuda_runtime.h>

#define NB 8
#define NC 256
#define NH 128
#define NW 128
#define NHW 16384
#define KK 1280
#define NP 25

// Output layout (float32, concatenated in reference-return order)
#define N_PATCH   65536000ULL                  // 8*1280*25*256
#define OFF_COORD 65536000ULL
#define OFF_OFFS  65556480ULL                  // + 8*1280*2
#define OFF_CAL   65556530ULL                  // + 50

static __device__ int2 g_coords[NB * KK];      // scratch: clamped (cy,cx) per (b,k)

// ---------------------------------------------------------------------------
// Kernel A: softmax + calibrated map + top-K selection (one block per batch)
// ---------------------------------------------------------------------------
__global__ __launch_bounds__(1024) void topk_kernel(
    const float* __restrict__ sal, const float* __restrict__ mask,
    float* __restrict__ out)
{
    const int b    = blockIdx.x;
    const int tid  = threadIdx.x;
    const int lane = tid & 31;
    const int wrp  = tid >> 5;

    __shared__ float red[32];
    __shared__ int   whist[8][256];            // privatized histogram (4 warps/copy)
    __shared__ int   hist2[256];
    __shared__ int   sh_b1, sh_cntgt, sh_T16, sh_cnt;
    __shared__ unsigned long long items[4096];

    const float* sb = sal + (size_t)b * NHW;

    // x = (saliency + mask) / TEMP, TEMP = 0.5 (exact *2)
    float x[16];
    float mx = -3.4e38f;
#pragma unroll
    for (int j = 0; j < 16; j++) {
        int i = tid + j * 1024;
        float v = (sb[i] + mask[i]) * 2.0f;
        x[j] = v;
        mx = fmaxf(mx, v);
    }
#pragma unroll
    for (int o = 16; o > 0; o >>= 1) mx = fmaxf(mx, __shfl_xor_sync(0xffffffffu, mx, o));
    if (lane == 0) red[wrp] = mx;
    __syncthreads();
    if (tid < 32) {
        float t = red[tid];
#pragma unroll
        for (int o = 16; o > 0; o >>= 1) t = fmaxf(t, __shfl_xor_sync(0xffffffffu, t, o));
        if (tid == 0) red[0] = t;
    }
    __syncthreads();
    const float gmax = red[0];
    __syncthreads();

    // e = exp(x - gmax), cached in x[]
    float sacc = 0.f;
#pragma unroll
    for (int j = 0; j < 16; j++) {
        float e = expf(x[j] - gmax);
        x[j] = e;
        sacc += e;
    }
#pragma unroll
    for (int o = 16; o > 0; o >>= 1) sacc += __shfl_xor_sync(0xffffffffu, sacc, o);
    if (lane == 0) red[wrp] = sacc;
    __syncthreads();
    if (tid < 32) {
        float t = red[tid];
#pragma unroll
        for (int o = 16; o > 0; o >>= 1) t += __shfl_xor_sync(0xffffffffu, t, o);
        if (tid == 0) red[0] = t;
    }
    __syncthreads();
    const float gsum = red[0];

    // soft values (same op order as jax: exp/sum); write calibrated map
#pragma unroll
    for (int j = 0; j < 16; j++) {
        int i = tid + j * 1024;
        float s = x[j] / gsum;
        x[j] = s;
        out[OFF_CAL + (unsigned long long)b * NHW + i] = s;
    }

    // ---- radix select level 1: top 8 bits, privatized histograms ----
    {
        int* h = &whist[0][0];
        for (int i = tid; i < 8 * 256; i += 1024) h[i] = 0;
    }
    __syncthreads();
    {
        int* myh = whist[wrp & 7];
#pragma unroll
        for (int j = 0; j < 16; j++) atomicAdd(&myh[__float_as_uint(x[j]) >> 24], 1);
    }
    __syncthreads();
    if (tid < 256) {
        int s = 0;
#pragma unroll
        for (int c = 0; c < 8; c++) s += whist[c][tid];
        hist2[tid] = s;
    }
    __syncthreads();
    if (tid == 0) {
        int cum = 0, bsel = 0;
        for (int bb = 255; bb >= 0; bb--) {
            int h = hist2[bb];
            if (cum + h >= KK) { bsel = bb; break; }
            cum += h;
        }
        sh_b1 = bsel; sh_cntgt = cum;
    }
    __syncthreads();
    const int b1 = sh_b1, cntgt = sh_cntgt;

    // ---- level 2: next 8 bits within threshold bin (few elements) ----
    if (tid < 256) hist2[tid] = 0;
    __syncthreads();
#pragma unroll
    for (int j = 0; j < 16; j++) {
        unsigned key = __float_as_uint(x[j]);
        if ((int)(key >> 24) == b1) atomicAdd(&hist2[(key >> 16) & 255], 1);
    }
    __syncthreads();
    if (tid == 0) {
        int K2 = KK - cntgt;
        int cum = 0, bsel = 0;
        for (int bb = 255; bb >= 0; bb--) {
            int h = hist2[bb];
            if (cum + h >= K2) { bsel = bb; break; }
            cum += h;
        }
        sh_T16 = (b1 << 8) | bsel;
        sh_cnt = 0;
    }
    __syncthreads();
    const unsigned T16 = (unsigned)sh_T16;

    // ---- collect survivors, warp-aggregated counter ----
#pragma unroll
    for (int j = 0; j < 16; j++) {
        unsigned key = __float_as_uint(x[j]);
        bool pred = (key >> 16) >= T16;
        unsigned m = __ballot_sync(0xffffffffu, pred);
        int base = 0;
        if (lane == 0 && m) base = atomicAdd(&sh_cnt, __popc(m));
        base = __shfl_sync(0xffffffffu, base, 0);
        if (pred) {
            int p = base + __popc(m & ((1u << lane) - 1u));
            if (p < 4096) {
                unsigned idx = (unsigned)(tid + j * 1024);
                // descending by soft, then ascending by index (jax tie-break)
                items[p] = ((unsigned long long)key << 32) | (unsigned)(~idx);
            }
        }
    }
    __syncthreads();
    int cnt = sh_cnt; if (cnt > 4096) cnt = 4096;
    const int n = (cnt <= 2048) ? 2048 : 4096;   // sort only what we must
    for (int i = cnt + tid; i < n; i += 1024) items[i] = 0ULL;
    __syncthreads();

    // ---- bitonic sort over n (2048 typical), descending ----
    for (int kk = 2; kk <= n; kk <<= 1) {
        for (int j = kk >> 1; j > 0; j >>= 1) {
            for (int i = tid; i < n; i += 1024) {
                int l = i ^ j;
                if (l > i) {
                    unsigned long long A = items[i], Bv = items[l];
                    bool desc = ((i & kk) == 0);
                    if (desc ? (A < Bv) : (A > Bv)) { items[i] = Bv; items[l] = A; }
                }
            }
            __syncthreads();
        }
    }

    // ---- emit coords ----
    for (int k = tid; k < KK; k += 1024) {
        unsigned long long it = items[k];
        unsigned idx = ~((unsigned)it);
        int cy = (int)(idx >> 7);
        int cx = (int)(idx & 127);
        cy = min(max(cy, 2), 125);
        cx = min(max(cx, 2), 125);
        unsigned long long o = OFF_COORD + ((unsigned long long)b * KK + k) * 2ULL;
        out[o]     = (float)cy;
        out[o + 1] = (float)cx;
        g_coords[b * KK + k] = make_int2(cy, cx);
    }

    // offsets output (constant), written once
    if (b == 0 && tid < 50) {
        int p = tid >> 1, j = tid & 1;
        int v = (j == 0 ? p / 5 : p % 5) - 2;
        out[OFF_OFFS + tid] = (float)v;
    }
}

// ---------------------------------------------------------------------------
// Kernel B v3: window gather + weighting. One block per (b,k) window.
// 512 threads: lane pair (2c, 2c+1) loads lo/hi 16B chunks of the same
// (channel,row) 128B line in ONE LDG.128 -> 1 L1 wavefront per line.
// NO shuffles: each lane stores only the window elements present in its own
// chunk (h=0: r+i<4, h=1: r+i>=4; each i covered exactly once). Stores are
// 16-active-lane, 16 consecutive channels = 64B = 1 wavefront.
// ---------------------------------------------------------------------------
__global__ __launch_bounds__(512) void gather_kernel(
    const float* __restrict__ feat, const float* __restrict__ gamma,
    float* __restrict__ out)
{
    const int blk = blockIdx.x;
    const int b = blk / KK;

    __shared__ float wts[NP];
    __shared__ int2  sc;
    if (threadIdx.x == 0) sc = g_coords[blk];
    __syncthreads();
    const int cy = sc.x, cx = sc.y;

    const int c = threadIdx.x >> 1;     // channel 0..255
    const int h = threadIdx.x & 1;      // lo/hi chunk
    const float* fb = feat + ((unsigned long long)b * NC + c) * NHW;

    const int xb = cx - 2;
    const int al = xb & ~3;             // float4-aligned start covering xb..xb+4
    const int r  = xb & 3;

    // Issue all 5 row loads early (MLP=5); each thread loads its 16B chunk.
    float4 own[5];
#pragma unroll
    for (int wy = 0; wy < 5; wy++) {
        int y = cy - 2 + wy;
        own[wy] = __ldg(reinterpret_cast<const float4*>(fb + y * NW + al) + h);
    }

    // Meanwhile warp 0 computes the 25 per-window weights.
    if (threadIdx.x < 32) {
        int lane = threadIdx.x;
        int dy = lane / 5 - 2, dx = lane % 5 - 2;
        const float g = __ldg(gamma);
        float scv = 0.f;
        if (lane < NP) {
            int y = cy + dy, xx = cx + dx;
            scv = out[OFF_CAL + (unsigned long long)b * NHW + y * NW + xx];
        }
        float sum = scv;
#pragma unroll
        for (int o = 16; o > 0; o >>= 1) sum += __shfl_xor_sync(0xffffffffu, sum, o);
        if (lane < NP) {
            float mean = sum / 25.0f;
            float dist = sqrtf((float)(dy * dy + dx * dx));
            float dw = expf(-dist / 2.5f);          // LAMBDA*WIN = 2.5
            float z = g * (scv - mean);
            float sg = 1.0f / (1.0f + expf(-z));
            wts[lane] = sg * dw;
        }
    }
    __syncthreads();

    float* ob = out + (unsigned long long)blk * NP * NC + c;

    // Each lane stores only elements its chunk holds. r is block-uniform, so
    // predication is warp-coherent: for each i, exactly one parity is active
    // (16 lanes, consecutive channels -> one 64B wavefront per store).
#pragma unroll
    for (int wy = 0; wy < 5; wy++) {
        float4 v = own[wy];
#pragma unroll
        for (int i = 0; i < 5; i++) {
            int s = r + i;                                   // 0..7
            bool active = h ? (s >= 4) : (s < 4);
            int t = s & 3;
            float val = (t == 0) ? v.x : (t == 1) ? v.y : (t == 2) ? v.z : v.w;
            if (active) {
                int p = wy * 5 + i;
                ob[(unsigned long long)p * NC] = val * wts[p];
            }
        }
    }
}

extern "C" void kernel_launch(void* const* d_in, const int* in_sizes, int n_in,
                              void* d_out, int out_size)
{
    (void)in_sizes; (void)n_in; (void)out_size;
    const float* feat  = (const float*)d_in[0];   // [8,256,128,128]
    const float* sal   = (const float*)d_in[1];   // [8,128,128]
    const float* mask  = (const float*)d_in[2];   // [1,128,128]
    const float* gamma = (const float*)d_in[3];   // [1]
    float* out = (float*)d_out;

    topk_kernel<<<NB, 1024>>>(sal, mask, out);
    gather_kernel<<<NB * KK, 512>>>(feat, gamma, out);
}

// round 8
// speedup vs baseline: 1.1109x; 1.0390x over previous
#include <cuda_runtime.h>

#define NB 8
#define NC 256
#define NH 128
#define NW 128
#define NHW 16384
#define KK 1280
#define NP 25

// Output layout (float32, concatenated in reference-return order)
#define N_PATCH   65536000ULL                  // 8*1280*25*256
#define OFF_COORD 65536000ULL
#define OFF_OFFS  65556480ULL                  // + 8*1280*2
#define OFF_CAL   65556530ULL                  // + 50

static __device__ int2  g_coords[NB * KK];     // clamped (cy,cx) per (b,k)
static __device__ float g_wts[NB * KK * 32];   // 25 weights per window (padded)

// ---------------------------------------------------------------------------
// Kernel A: softmax + calibrated map + top-K selection (one block per batch)
// ---------------------------------------------------------------------------
__global__ __launch_bounds__(1024) void topk_kernel(
    const float* __restrict__ sal, const float* __restrict__ mask,
    float* __restrict__ out)
{
    const int b    = blockIdx.x;
    const int tid  = threadIdx.x;
    const int lane = tid & 31;
    const int wrp  = tid >> 5;

    __shared__ float red[32];
    __shared__ int   whist[8][256];            // privatized histogram (4 warps/copy)
    __shared__ int   hist2[256];
    __shared__ int   sh_b1, sh_cntgt, sh_T16, sh_cnt;
    __shared__ unsigned long long items[4096];

    const float* sb = sal + (size_t)b * NHW;

    // x = (saliency + mask) / TEMP, TEMP = 0.5 (exact *2)
    float x[16];
    float mx = -3.4e38f;
#pragma unroll
    for (int j = 0; j < 16; j++) {
        int i = tid + j * 1024;
        float v = (sb[i] + mask[i]) * 2.0f;
        x[j] = v;
        mx = fmaxf(mx, v);
    }
#pragma unroll
    for (int o = 16; o > 0; o >>= 1) mx = fmaxf(mx, __shfl_xor_sync(0xffffffffu, mx, o));
    if (lane == 0) red[wrp] = mx;
    __syncthreads();
    if (tid < 32) {
        float t = red[tid];
#pragma unroll
        for (int o = 16; o > 0; o >>= 1) t = fmaxf(t, __shfl_xor_sync(0xffffffffu, t, o));
        if (tid == 0) red[0] = t;
    }
    __syncthreads();
    const float gmax = red[0];
    __syncthreads();

    // e = exp(x - gmax), cached in x[]
    float sacc = 0.f;
#pragma unroll
    for (int j = 0; j < 16; j++) {
        float e = expf(x[j] - gmax);
        x[j] = e;
        sacc += e;
    }
#pragma unroll
    for (int o = 16; o > 0; o >>= 1) sacc += __shfl_xor_sync(0xffffffffu, sacc, o);
    if (lane == 0) red[wrp] = sacc;
    __syncthreads();
    if (tid < 32) {
        float t = red[tid];
#pragma unroll
        for (int o = 16; o > 0; o >>= 1) t += __shfl_xor_sync(0xffffffffu, t, o);
        if (tid == 0) red[0] = t;
    }
    __syncthreads();
    const float gsum = red[0];

    // soft values (same op order as jax: exp/sum); write calibrated map
#pragma unroll
    for (int j = 0; j < 16; j++) {
        int i = tid + j * 1024;
        float s = x[j] / gsum;
        x[j] = s;
        out[OFF_CAL + (unsigned long long)b * NHW + i] = s;
    }

    // ---- radix select level 1: top 8 bits, privatized histograms ----
    {
        int* h = &whist[0][0];
        for (int i = tid; i < 8 * 256; i += 1024) h[i] = 0;
    }
    __syncthreads();
    {
        int* myh = whist[wrp & 7];
#pragma unroll
        for (int j = 0; j < 16; j++) atomicAdd(&myh[__float_as_uint(x[j]) >> 24], 1);
    }
    __syncthreads();
    if (tid < 256) {
        int s = 0;
#pragma unroll
        for (int c = 0; c < 8; c++) s += whist[c][tid];
        hist2[tid] = s;
    }
    __syncthreads();
    if (tid == 0) {
        int cum = 0, bsel = 0;
        for (int bb = 255; bb >= 0; bb--) {
            int h = hist2[bb];
            if (cum + h >= KK) { bsel = bb; break; }
            cum += h;
        }
        sh_b1 = bsel; sh_cntgt = cum;
    }
    __syncthreads();
    const int b1 = sh_b1, cntgt = sh_cntgt;

    // ---- level 2: next 8 bits within threshold bin (few elements) ----
    if (tid < 256) hist2[tid] = 0;
    __syncthreads();
#pragma unroll
    for (int j = 0; j < 16; j++) {
        unsigned key = __float_as_uint(x[j]);
        if ((int)(key >> 24) == b1) atomicAdd(&hist2[(key >> 16) & 255], 1);
    }
    __syncthreads();
    if (tid == 0) {
        int K2 = KK - cntgt;
        int cum = 0, bsel = 0;
        for (int bb = 255; bb >= 0; bb--) {
            int h = hist2[bb];
            if (cum + h >= K2) { bsel = bb; break; }
            cum += h;
        }
        sh_T16 = (b1 << 8) | bsel;
        sh_cnt = 0;
    }
    __syncthreads();
    const unsigned T16 = (unsigned)sh_T16;

    // ---- collect survivors, warp-aggregated counter ----
#pragma unroll
    for (int j = 0; j < 16; j++) {
        unsigned key = __float_as_uint(x[j]);
        bool pred = (key >> 16) >= T16;
        unsigned m = __ballot_sync(0xffffffffu, pred);
        int base = 0;
        if (lane == 0 && m) base = atomicAdd(&sh_cnt, __popc(m));
        base = __shfl_sync(0xffffffffu, base, 0);
        if (pred) {
            int p = base + __popc(m & ((1u << lane) - 1u));
            if (p < 4096) {
                unsigned idx = (unsigned)(tid + j * 1024);
                // descending by soft, then ascending by index (jax tie-break)
                items[p] = ((unsigned long long)key << 32) | (unsigned)(~idx);
            }
        }
    }
    __syncthreads();
    int cnt = sh_cnt; if (cnt > 4096) cnt = 4096;
    const int n = (cnt <= 2048) ? 2048 : 4096;   // sort only what we must
    for (int i = cnt + tid; i < n; i += 1024) items[i] = 0ULL;
    __syncthreads();

    // ---- bitonic sort over n (2048 typical), descending ----
    for (int kk = 2; kk <= n; kk <<= 1) {
        for (int j = kk >> 1; j > 0; j >>= 1) {
            for (int i = tid; i < n; i += 1024) {
                int l = i ^ j;
                if (l > i) {
                    unsigned long long A = items[i], Bv = items[l];
                    bool desc = ((i & kk) == 0);
                    if (desc ? (A < Bv) : (A > Bv)) { items[i] = Bv; items[l] = A; }
                }
            }
            __syncthreads();
        }
    }

    // ---- emit coords ----
    for (int k = tid; k < KK; k += 1024) {
        unsigned long long it = items[k];
        unsigned idx = ~((unsigned)it);
        int cy = (int)(idx >> 7);
        int cx = (int)(idx & 127);
        cy = min(max(cy, 2), 125);
        cx = min(max(cx, 2), 125);
        unsigned long long o = OFF_COORD + ((unsigned long long)b * KK + k) * 2ULL;
        out[o]     = (float)cy;
        out[o + 1] = (float)cx;
        g_coords[b * KK + k] = make_int2(cy, cx);
    }

    // offsets output (constant), written once
    if (b == 0 && tid < 50) {
        int p = tid >> 1, j = tid & 1;
        int v = (j == 0 ? p / 5 : p % 5) - 2;
        out[OFF_OFFS + tid] = (float)v;
    }
}

// ---------------------------------------------------------------------------
// Kernel W: per-window weights. One warp per window; identical arithmetic to
// the previous in-gather computation (shfl tree over 32 lanes, zeros padded).
// ---------------------------------------------------------------------------
__global__ __launch_bounds__(256) void weights_kernel(
    const float* __restrict__ gamma, const float* __restrict__ out)
{
    const int w = blockIdx.x * 8 + (threadIdx.x >> 5);
    const int lane = threadIdx.x & 31;
    const int b = w / KK;

    const int2 sc = g_coords[w];
    const int dy = lane / 5 - 2, dx = lane % 5 - 2;
    const float g = __ldg(gamma);

    float scv = 0.f;
    if (lane < NP) {
        int y = sc.x + dy, xx = sc.y + dx;
        scv = __ldg(&out[OFF_CAL + (unsigned long long)b * NHW + y * NW + xx]);
    }
    float sum = scv;
#pragma unroll
    for (int o = 16; o > 0; o >>= 1) sum += __shfl_xor_sync(0xffffffffu, sum, o);
    if (lane < NP) {
        float mean = sum / 25.0f;
        float dist = sqrtf((float)(dy * dy + dx * dx));
        float dw = expf(-dist / 2.5f);          // LAMBDA*WIN = 2.5
        float z = g * (scv - mean);
        float sg = 1.0f / (1.0f + expf(-z));
        g_wts[w * 32 + lane] = sg * dw;
    }
}

// ---------------------------------------------------------------------------
// Kernel B v4: window gather. One block per (b,k) window, 512 threads.
// Lane pair (2c, 2c+1) loads lo/hi 16B chunks of the same (channel,row)
// 128B line in ONE LDG.128 -> 1 L1 wavefront per line. No weight compute:
// coords broadcast-loaded per-thread so the 5 feat loads issue immediately;
// the single __syncthreads only covers a 25-float smem copy that overlaps
// with the in-flight feat loads. Stores: 16-lane / 64B, warp-coherent.
// ---------------------------------------------------------------------------
__global__ __launch_bounds__(512) void gather_kernel(
    const float* __restrict__ feat, float* __restrict__ out)
{
    const int blk = blockIdx.x;
    const int b = blk / KK;

    const int2 sc = __ldg(&g_coords[blk]);     // broadcast load, all threads
    const int cy = sc.x, cx = sc.y;

    const int c = threadIdx.x >> 1;     // channel 0..255
    const int h = threadIdx.x & 1;      // lo/hi chunk
    const float* fb = feat + ((unsigned long long)b * NC + c) * NHW;

    const int xb = cx - 2;
    const int al = xb & ~3;             // float4-aligned start covering xb..xb+4
    const int r  = xb & 3;

    // Issue all 5 row loads immediately (MLP=5).
    float4 own[5];
#pragma unroll
    for (int wy = 0; wy < 5; wy++) {
        int y = cy - 2 + wy;
        own[wy] = __ldg(reinterpret_cast<const float4*>(fb + y * NW + al) + h);
    }

    // Copy precomputed weights to smem (overlaps with feat-load latency).
    __shared__ float wts[NP];
    if (threadIdx.x < NP) wts[threadIdx.x] = __ldg(&g_wts[blk * 32 + threadIdx.x]);
    __syncthreads();

    float* ob = out + (unsigned long long)blk * NP * NC + c;

    // Each lane stores only elements its chunk holds (h=0: r+i<4, h=1: r+i>=4).
    // r is block-uniform -> warp-coherent predication; 16 consecutive channels
    // per active store = one 64B wavefront.
#pragma unroll
    for (int wy = 0; wy < 5; wy++) {
        float4 v = own[wy];
#pragma unroll
        for (int i = 0; i < 5; i++) {
            int s = r + i;                                   // 0..7
            bool active = h ? (s >= 4) : (s < 4);
            int t = s & 3;
            float val = (t == 0) ? v.x : (t == 1) ? v.y : (t == 2) ? v.z : v.w;
            if (active) {
                int p = wy * 5 + i;
                ob[(unsigned long long)p * NC] = val * wts[p];
            }
        }
    }
}

extern "C" void kernel_launch(void* const* d_in, const int* in_sizes, int n_in,
                              void* d_out, int out_size)
{
    (void)in_sizes; (void)n_in; (void)out_size;
    const float* feat  = (const float*)d_in[0];   // [8,256,128,128]
    const float* sal   = (const float*)d_in[1];   // [8,128,128]
    const float* mask  = (const float*)d_in[2];   // [1,128,128]
    const float* gamma = (const float*)d_in[3];   // [1]
    float* out = (float*)d_out;

    topk_kernel<<<NB, 1024>>>(sal, mask, out);
    weights_kernel<<<NB * KK / 8, 256>>>(gamma, out);
    gather_kernel<<<NB * KK, 512>>>(feat, out);
}